// round 2
// baseline (speedup 1.0000x reference)
#include <cuda_runtime.h>
#include <cstdint>

#define N_NODES 100000
#define N_EDGES 1600000
#define D 64            // D_IN == D_OUT == 64
#define VEC_PER_ROW 16  // 64 floats = 16 float4

// ---------------------------------------------------------------------------
// Kernel 1: zero the output accumulator (d_out is poisoned to 0xAA)
// ---------------------------------------------------------------------------
__global__ void zero_kernel(float4* __restrict__ out, int n4) {
    int i = blockIdx.x * blockDim.x + threadIdx.x;
    int stride = gridDim.x * blockDim.x;
    float4 z = make_float4(0.f, 0.f, 0.f, 0.f);
    for (; i < n4; i += stride) out[i] = z;
}

// ---------------------------------------------------------------------------
// Kernel 2: edge-parallel scatter-add of raw features into d_out.
// 16 consecutive threads handle one edge: thread (e, part) gathers
// feature[src[e]] float4 #part and red.add.v4.f32's it into out[dst[e]].
// Both the 25.6MB feature table and the 25.6MB accumulator are L2-resident.
// ---------------------------------------------------------------------------
__global__ void scatter_kernel(const float4* __restrict__ feat4,
                               const int*    __restrict__ src,
                               const int*    __restrict__ dst,
                               float*        __restrict__ out) {
    long long idx = (long long)blockIdx.x * blockDim.x + threadIdx.x;
    int e    = (int)(idx >> 4);
    int part = (int)(idx & 15);
    if (e >= N_EDGES) return;

    int u = __ldg(&src[e]);
    int v = __ldg(&dst[e]);

    float4 m = __ldg(&feat4[(size_t)u * VEC_PER_ROW + part]);
    float* p = out + (size_t)v * D + part * 4;

    asm volatile("red.global.add.v4.f32 [%0], {%1,%2,%3,%4};"
                 :: "l"(p), "f"(m.x), "f"(m.y), "f"(m.z), "f"(m.w)
                 : "memory");
}

// ---------------------------------------------------------------------------
// Kernel 3: in-place per-row transform: out[v] = h[v] @ W^T + b
// Block = 256 threads = 4 rows. W is staged transposed (Wt[k][j]) into
// padded shared memory so the inner-loop reads are conflict-free.
// ---------------------------------------------------------------------------
__global__ void transform_kernel(float* __restrict__ out,
                                 const float* __restrict__ W,
                                 const float* __restrict__ b) {
    __shared__ float Wt[D * 65];       // Wt[k*65 + j] = W[j*64 + k], padded
    __shared__ float rowsh[4][D];

    int tid = threadIdx.x;

    // Cooperative transposed load of W (4096 floats / 256 threads = 16 each)
    #pragma unroll
    for (int i = tid; i < D * D; i += 256) {
        int j = i >> 6;       // output index
        int k = i & 63;       // input index
        Wt[k * 65 + j] = W[i];
    }

    int rid  = tid >> 6;      // 0..3  (row within block)
    int j    = tid & 63;      // output feature index
    int node = blockIdx.x * 4 + rid;

    float bj = __ldg(&b[j]);

    if (node < N_NODES) {
        rowsh[rid][j] = out[(size_t)node * D + j];
    }
    __syncthreads();

    if (node < N_NODES) {
        float acc = bj;
        #pragma unroll
        for (int k = 0; k < D; k++) {
            acc = fmaf(rowsh[rid][k], Wt[k * 65 + j], acc);
        }
        out[(size_t)node * D + j] = acc;
    }
}

// ---------------------------------------------------------------------------
// Launch
// ---------------------------------------------------------------------------
extern "C" void kernel_launch(void* const* d_in, const int* in_sizes, int n_in,
                              void* d_out, int out_size) {
    const float* feature = (const float*)d_in[0];   // [100000, 64]
    const int*   src     = (const int*)  d_in[1];   // [1600000]
    const int*   dst     = (const int*)  d_in[2];   // [1600000]
    const float* W       = (const float*)d_in[3];   // [64, 64]
    const float* b       = (const float*)d_in[4];   // [64]
    float*       out     = (float*)d_out;           // [100000, 64]

    // 1) zero the accumulator
    int n4 = N_NODES * D / 4;                       // 1.6M float4
    zero_kernel<<<2048, 256>>>((float4*)out, n4);

    // 2) scatter-add raw features (edge-parallel, 16 threads/edge)
    long long total = (long long)N_EDGES * VEC_PER_ROW;   // 25.6M work items
    int blocks = (int)((total + 255) / 256);              // 100000 blocks
    scatter_kernel<<<blocks, 256>>>((const float4*)feature, src, dst, out);

    // 3) in-place linear transform + bias
    transform_kernel<<<(N_NODES + 3) / 4, 256>>>(out, W, b);
}